// round 15
// baseline (speedup 1.0000x reference)
#include <cuda_runtime.h>
#include <cstdint>

// StreamingSTFT collapses analytically:
//   irfft(rfft(x)) == x  =>  frame = in_buf * aw * sw
//   sw nonzero only on [96,160)  =>  overlap-add reduces to
//   out[i][j] = chunk[i-3][j] * W[j]   (i >= 3), else 0
//   W[j] = aw[j+128]*sw[j+128] (j<32) ; aw[j+64]*sw[j+64] (j>=32)
//
// FINAL (R8 config; identical-source draws {10.37, 10.91, 10.50, 10.24}us.
// Best draw = 6.25 TB/s through the LTS crossbar ~= 91% of the ~6300 B/cyc
// path-independent ceiling for the mandatory 64 MB of traffic — the
// binder; DRAM sits at ~37% of its own peak):
//   - 148*8 = 1184 blocks x 256 threads: 64 warps/SM, single perfectly
//     balanced wave (no 6-vs-7 block tail, no wave transitions)
//   - 7 front-batched independent __ldg float4 loads (MLP=7) then stores
//   - window product hoisted (stride % 16 == 0 keeps lane column fixed)
//   - all index math 32-bit (max index 2^21-1)
// Measured regressions, deliberately absent: 256-bit (.v8) accesses,
// L2 eviction policies (bytes cross the LTS regardless), unbalanced
// grids. Remaining variance is clock/DVFS noise, not code.

static constexpr int HOP = 64;
static constexpr int NUM_FRAMES = 131072;
static constexpr int N_VEC4 = NUM_FRAMES * HOP / 4;        // 2,097,152
static constexpr int DELAY_VEC4 = (3 * HOP) / 4;           // 48 float4s

static constexpr int NUM_SMS = 148;
static constexpr int BLOCKS  = NUM_SMS * 8;                // 1184
static constexpr int THREADS = 256;
static constexpr int STRIDE  = BLOCKS * THREADS;           // 303104, %16 == 0
static constexpr int ITERS   = 7;                          // 6 full + 1 partial

__global__ void __launch_bounds__(THREADS, 8)
stft_delay_scale_kernel(const float4* __restrict__ chunk4,
                        const float*  __restrict__ aw,
                        const float*  __restrict__ sw,
                        float4* __restrict__ out4)
{
    const int i0 = blockIdx.x * THREADS + threadIdx.x;

    // Column of this lane within the 64-wide row; invariant across the
    // strided loop because STRIDE % 16 == 0.
    const int j0   = (i0 & 15) << 2;
    const int base = j0 + (j0 < 32 ? 128 : 64);            // float4-aligned

    const float4 a = *reinterpret_cast<const float4*>(aw + base);
    const float4 s = *reinterpret_cast<const float4*>(sw + base);
    const float4 w = make_float4(a.x * s.x, a.y * s.y, a.z * s.z, a.w * s.w);

    // Front-batch all independent loads (MLP = 7; only iter 6 is guarded).
    float4 v[ITERS];
#pragma unroll
    for (int k = 0; k < ITERS; k++) {
        const int i = i0 + k * STRIDE;                     // 32-bit, exact
        const bool in_range = (k < ITERS - 1) || (i < N_VEC4);
        if (in_range && i >= DELAY_VEC4) {
            v[k] = __ldg(chunk4 + (i - DELAY_VEC4));
        } else {
            v[k] = make_float4(0.f, 0.f, 0.f, 0.f);
        }
    }

#pragma unroll
    for (int k = 0; k < ITERS; k++) {
        const int i = i0 + k * STRIDE;
        if (k < ITERS - 1 || i < N_VEC4) {
            float4 o;
            o.x = v[k].x * w.x;
            o.y = v[k].y * w.y;
            o.z = v[k].z * w.z;
            o.w = v[k].w * w.w;
            out4[i] = o;
        }
    }
}

extern "C" void kernel_launch(void* const* d_in, const int* in_sizes, int n_in,
                              void* d_out, int out_size)
{
    const float4* chunk4 = reinterpret_cast<const float4*>(d_in[0]);
    const float*  aw     = reinterpret_cast<const float*>(d_in[1]);
    const float*  sw     = reinterpret_cast<const float*>(d_in[2]);
    float4*       out4   = reinterpret_cast<float4*>(d_out);

    stft_delay_scale_kernel<<<BLOCKS, THREADS>>>(chunk4, aw, sw, out4);
}